// round 2
// baseline (speedup 1.0000x reference)
#include <cuda_runtime.h>

// Problem constants
#define BB  4
#define TT  2048
#define CC  1024
#define NH_ 16
#define HS_ 64
#define HB_ (BB * NH_)   // 64 (b,h) pairs

// Scratch (device globals — no allocation allowed)
__device__ float g_q[BB * NH_ * TT * HS_];   // [B,NH,T,HS]
__device__ float g_k[BB * NH_ * TT * HS_];
__device__ float g_v[BB * NH_ * TT * HS_];
__device__ float g_y[BB * TT * CC];          // [B,T,NH,HS] == [B,T,C]

// ---------------------------------------------------------------------------
// Kernel 1: qkv = x @ W_attn^T, scatter into g_q/g_k/g_v in [B,NH,T,HS] layout
// A: x [8192,1024] row-major; W: [3072,1024] row-major (so W^T is used)
// Tile: BM=128, BN=128, BK=16; 256 threads; 8x8 per thread (split 4+4 halves)
// ---------------------------------------------------------------------------
__global__ __launch_bounds__(256) void qkv_gemm_kernel(
    const float* __restrict__ A, const float* __restrict__ W)
{
    const int K = CC;
    __shared__ float As[16][128];
    __shared__ float Bs[16][128];

    const int tid = threadIdx.x;
    const int bn = blockIdx.x, bm = blockIdx.y;
    const int lr = tid >> 2, lq = tid & 3;    // loader: row, k-quad
    const int ty = tid >> 4, tx = tid & 15;   // compute: 16x16 grid

    const float* Ab = A + (size_t)(bm * 128 + lr) * K + lq * 4;
    const float* Bb = W + (size_t)(bn * 128 + lr) * K + lq * 4;

    float acc[8][8];
#pragma unroll
    for (int i = 0; i < 8; i++)
#pragma unroll
        for (int j = 0; j < 8; j++) acc[i][j] = 0.0f;

    for (int k0 = 0; k0 < K; k0 += 16) {
        float4 a0 = *(const float4*)(Ab + k0);
        float4 a1 = *(const float4*)(Ab + (size_t)64 * K + k0);
        float4 b0 = *(const float4*)(Bb + k0);
        float4 b1 = *(const float4*)(Bb + (size_t)64 * K + k0);
        __syncthreads();
        As[lq*4+0][lr] = a0.x; As[lq*4+1][lr] = a0.y; As[lq*4+2][lr] = a0.z; As[lq*4+3][lr] = a0.w;
        As[lq*4+0][lr+64] = a1.x; As[lq*4+1][lr+64] = a1.y; As[lq*4+2][lr+64] = a1.z; As[lq*4+3][lr+64] = a1.w;
        Bs[lq*4+0][lr] = b0.x; Bs[lq*4+1][lr] = b0.y; Bs[lq*4+2][lr] = b0.z; Bs[lq*4+3][lr] = b0.w;
        Bs[lq*4+0][lr+64] = b1.x; Bs[lq*4+1][lr+64] = b1.y; Bs[lq*4+2][lr+64] = b1.z; Bs[lq*4+3][lr+64] = b1.w;
        __syncthreads();
#pragma unroll
        for (int kk = 0; kk < 16; kk++) {
            float4 xa0 = *(const float4*)&As[kk][ty * 4];
            float4 xa1 = *(const float4*)&As[kk][64 + ty * 4];
            float4 xb0 = *(const float4*)&Bs[kk][tx * 4];
            float4 xb1 = *(const float4*)&Bs[kk][64 + tx * 4];
            float ra[8] = {xa0.x, xa0.y, xa0.z, xa0.w, xa1.x, xa1.y, xa1.z, xa1.w};
            float rb[8] = {xb0.x, xb0.y, xb0.z, xb0.w, xb1.x, xb1.y, xb1.z, xb1.w};
#pragma unroll
            for (int i = 0; i < 8; i++)
#pragma unroll
                for (int j = 0; j < 8; j++)
                    acc[i][j] += ra[i] * rb[j];
        }
    }

    // Epilogue: scatter to q/k/v in [B,NH,T,HS]
#pragma unroll
    for (int i = 0; i < 8; i++) {
        int row = bm * 128 + ((i < 4) ? (ty * 4 + i) : (64 + ty * 4 + i - 4));
        int b_ = row >> 11;          // /2048
        int t  = row & 2047;
#pragma unroll
        for (int jc = 0; jc < 2; jc++) {
            int n = bn * 128 + jc * 64 + tx * 4;
            int which = n >> 10;
            int c = n & 1023;
            int head = c >> 6;
            int d = c & 63;
            float* dst = (which == 0) ? g_q : ((which == 1) ? g_k : g_v);
            float4 val = make_float4(acc[i][jc*4+0], acc[i][jc*4+1], acc[i][jc*4+2], acc[i][jc*4+3]);
            *(float4*)&dst[(((size_t)(b_ * NH_ + head)) * TT + t) * HS_ + d] = val;
        }
    }
}

// ---------------------------------------------------------------------------
// Kernel 2: causal flash attention, fp32. One block per (head, 64-query tile).
// Q,K kept transposed in smem ([d][row]) for conflict-free vectorized S loop.
// P reuses K's buffer. Exactly 48KB static smem.
// ---------------------------------------------------------------------------
__global__ __launch_bounds__(256) void flash_kernel()
{
    __shared__ float Qts[64][64];  // [d][r], pre-scaled by 1/sqrt(hs)
    __shared__ float KPs[64][64];  // K as [d][c]; reused as P [r][c]
    __shared__ float Vs[64][64];   // [c][dv]

    const int qt = blockIdx.x, hb = blockIdx.y;
    const int tid = threadIdx.x;
    const int ty = tid >> 4, tx = tid & 15;
    const int lr = tid >> 2, lc = tid & 3;   // loader: row lr, 16 cols at lc*16

    const float* qp = g_q + ((size_t)hb * TT + qt * 64) * HS_;
#pragma unroll
    for (int u = 0; u < 4; u++) {
        float4 v = *(const float4*)(qp + lr * 64 + lc * 16 + u * 4);
        int d0 = lc * 16 + u * 4;
        Qts[d0+0][lr] = v.x * 0.125f;
        Qts[d0+1][lr] = v.y * 0.125f;
        Qts[d0+2][lr] = v.z * 0.125f;
        Qts[d0+3][lr] = v.w * 0.125f;
    }

    float o[4][4];
    float mi[4], li[4];
#pragma unroll
    for (int i = 0; i < 4; i++) {
        mi[i] = -1e30f; li[i] = 0.0f;
#pragma unroll
        for (int j = 0; j < 4; j++) o[i][j] = 0.0f;
    }

    for (int kt = 0; kt <= qt; kt++) {
        const float* kp = g_k + ((size_t)hb * TT + kt * 64) * HS_;
        const float* vp = g_v + ((size_t)hb * TT + kt * 64) * HS_;
#pragma unroll
        for (int u = 0; u < 4; u++) {
            int d0 = lc * 16 + u * 4;
            float4 kv = *(const float4*)(kp + lr * 64 + d0);
            KPs[d0+0][lr] = kv.x; KPs[d0+1][lr] = kv.y; KPs[d0+2][lr] = kv.z; KPs[d0+3][lr] = kv.w;
            float4 vv = *(const float4*)(vp + lr * 64 + d0);
            *(float4*)&Vs[lr][d0] = vv;
        }
        __syncthreads();

        // S = Q K^T (scaled already)
        float s[4][4];
#pragma unroll
        for (int i = 0; i < 4; i++)
#pragma unroll
            for (int j = 0; j < 4; j++) s[i][j] = 0.0f;

#pragma unroll 8
        for (int d = 0; d < 64; d++) {
            float4 q4 = *(const float4*)&Qts[d][ty * 4];
            float4 k4 = *(const float4*)&KPs[d][tx * 4];
            float qa[4] = {q4.x, q4.y, q4.z, q4.w};
            float ka[4] = {k4.x, k4.y, k4.z, k4.w};
#pragma unroll
            for (int i = 0; i < 4; i++)
#pragma unroll
                for (int j = 0; j < 4; j++)
                    s[i][j] += qa[i] * ka[j];
        }

        if (kt == qt) {
#pragma unroll
            for (int i = 0; i < 4; i++)
#pragma unroll
                for (int j = 0; j < 4; j++)
                    if (tx * 4 + j > ty * 4 + i) s[i][j] = -1e30f;
        }

        // Online softmax (16 lanes share each row group)
#pragma unroll
        for (int i = 0; i < 4; i++) {
            float rm = fmaxf(fmaxf(s[i][0], s[i][1]), fmaxf(s[i][2], s[i][3]));
            rm = fmaxf(rm, __shfl_xor_sync(0xffffffffu, rm, 1));
            rm = fmaxf(rm, __shfl_xor_sync(0xffffffffu, rm, 2));
            rm = fmaxf(rm, __shfl_xor_sync(0xffffffffu, rm, 4));
            rm = fmaxf(rm, __shfl_xor_sync(0xffffffffu, rm, 8));
            float mnew = fmaxf(mi[i], rm);
            float corr = __expf(mi[i] - mnew);
            float p0 = __expf(s[i][0] - mnew);
            float p1 = __expf(s[i][1] - mnew);
            float p2 = __expf(s[i][2] - mnew);
            float p3 = __expf(s[i][3] - mnew);
            float rs = p0 + p1 + p2 + p3;
            rs += __shfl_xor_sync(0xffffffffu, rs, 1);
            rs += __shfl_xor_sync(0xffffffffu, rs, 2);
            rs += __shfl_xor_sync(0xffffffffu, rs, 4);
            rs += __shfl_xor_sync(0xffffffffu, rs, 8);
            li[i] = li[i] * corr + rs;
            mi[i] = mnew;
            o[i][0] *= corr; o[i][1] *= corr; o[i][2] *= corr; o[i][3] *= corr;
            s[i][0] = p0; s[i][1] = p1; s[i][2] = p2; s[i][3] = p3;
        }

        __syncthreads();  // all Kts reads done before overwriting with P
#pragma unroll
        for (int i = 0; i < 4; i++)
            *(float4*)&KPs[ty * 4 + i][tx * 4] = make_float4(s[i][0], s[i][1], s[i][2], s[i][3]);
        __syncthreads();

        // O += P @ V
#pragma unroll 4
        for (int c4 = 0; c4 < 16; c4++) {
            float4 v0 = *(const float4*)&Vs[c4 * 4 + 0][tx * 4];
            float4 v1 = *(const float4*)&Vs[c4 * 4 + 1][tx * 4];
            float4 v2 = *(const float4*)&Vs[c4 * 4 + 2][tx * 4];
            float4 v3 = *(const float4*)&Vs[c4 * 4 + 3][tx * 4];
#pragma unroll
            for (int i = 0; i < 4; i++) {
                float4 pr = *(const float4*)&KPs[ty * 4 + i][c4 * 4];
                o[i][0] += pr.x * v0.x + pr.y * v1.x + pr.z * v2.x + pr.w * v3.x;
                o[i][1] += pr.x * v0.y + pr.y * v1.y + pr.z * v2.y + pr.w * v3.y;
                o[i][2] += pr.x * v0.z + pr.y * v1.z + pr.z * v2.z + pr.w * v3.z;
                o[i][3] += pr.x * v0.w + pr.y * v1.w + pr.z * v2.w + pr.w * v3.w;
            }
        }
        __syncthreads();  // protect KPs/Vs before next iteration's loads
    }

    // Write O in [B,T,NH,HS] layout
    const int b_ = hb >> 4, h = hb & 15;
#pragma unroll
    for (int i = 0; i < 4; i++) {
        float inv = 1.0f / li[i];
        int t = qt * 64 + ty * 4 + i;
        float4 val = make_float4(o[i][0] * inv, o[i][1] * inv, o[i][2] * inv, o[i][3] * inv);
        *(float4*)&g_y[(((size_t)(b_ * TT + t)) * NH_ + h) * HS_ + tx * 4] = val;
    }
}

// ---------------------------------------------------------------------------
// Kernel 3: out = g_y @ W_proj^T.  Same tiling as kernel 1, plain store.
// ---------------------------------------------------------------------------
__global__ __launch_bounds__(256) void proj_gemm_kernel(
    const float* __restrict__ W, float* __restrict__ out)
{
    const int K = CC;
    __shared__ float As[16][128];
    __shared__ float Bs[16][128];

    const int tid = threadIdx.x;
    const int bn = blockIdx.x, bm = blockIdx.y;
    const int lr = tid >> 2, lq = tid & 3;
    const int ty = tid >> 4, tx = tid & 15;

    const float* Ab = g_y + (size_t)(bm * 128 + lr) * K + lq * 4;
    const float* Bb = W + (size_t)(bn * 128 + lr) * K + lq * 4;

    float acc[8][8];
#pragma unroll
    for (int i = 0; i < 8; i++)
#pragma unroll
        for (int j = 0; j < 8; j++) acc[i][j] = 0.0f;

    for (int k0 = 0; k0 < K; k0 += 16) {
        float4 a0 = *(const float4*)(Ab + k0);
        float4 a1 = *(const float4*)(Ab + (size_t)64 * K + k0);
        float4 b0 = *(const float4*)(Bb + k0);
        float4 b1 = *(const float4*)(Bb + (size_t)64 * K + k0);
        __syncthreads();
        As[lq*4+0][lr] = a0.x; As[lq*4+1][lr] = a0.y; As[lq*4+2][lr] = a0.z; As[lq*4+3][lr] = a0.w;
        As[lq*4+0][lr+64] = a1.x; As[lq*4+1][lr+64] = a1.y; As[lq*4+2][lr+64] = a1.z; As[lq*4+3][lr+64] = a1.w;
        Bs[lq*4+0][lr] = b0.x; Bs[lq*4+1][lr] = b0.y; Bs[lq*4+2][lr] = b0.z; Bs[lq*4+3][lr] = b0.w;
        Bs[lq*4+0][lr+64] = b1.x; Bs[lq*4+1][lr+64] = b1.y; Bs[lq*4+2][lr+64] = b1.z; Bs[lq*4+3][lr+64] = b1.w;
        __syncthreads();
#pragma unroll
        for (int kk = 0; kk < 16; kk++) {
            float4 xa0 = *(const float4*)&As[kk][ty * 4];
            float4 xa1 = *(const float4*)&As[kk][64 + ty * 4];
            float4 xb0 = *(const float4*)&Bs[kk][tx * 4];
            float4 xb1 = *(const float4*)&Bs[kk][64 + tx * 4];
            float ra[8] = {xa0.x, xa0.y, xa0.z, xa0.w, xa1.x, xa1.y, xa1.z, xa1.w};
            float rb[8] = {xb0.x, xb0.y, xb0.z, xb0.w, xb1.x, xb1.y, xb1.z, xb1.w};
#pragma unroll
            for (int i = 0; i < 8; i++)
#pragma unroll
                for (int j = 0; j < 8; j++)
                    acc[i][j] += ra[i] * rb[j];
        }
    }

#pragma unroll
    for (int i = 0; i < 8; i++) {
        int row = bm * 128 + ((i < 4) ? (ty * 4 + i) : (64 + ty * 4 + i - 4));
#pragma unroll
        for (int jc = 0; jc < 2; jc++) {
            int n = bn * 128 + jc * 64 + tx * 4;
            float4 val = make_float4(acc[i][jc*4+0], acc[i][jc*4+1], acc[i][jc*4+2], acc[i][jc*4+3]);
            *(float4*)&out[(size_t)row * CC + n] = val;
        }
    }
}

// ---------------------------------------------------------------------------
extern "C" void kernel_launch(void* const* d_in, const int* in_sizes, int n_in,
                              void* d_out, int out_size)
{
    const float* x      = (const float*)d_in[0];  // [B,T,C]
    const float* W_attn = (const float*)d_in[1];  // [3C,C]
    const float* W_proj = (const float*)d_in[2];  // [C,C]
    // d_in[3..6] (pos_emb, W_fc, W_cproj, ln_w) feed a discarded branch — skipped.
    float* out = (float*)d_out;                   // [B,T,C] fp32

    qkv_gemm_kernel<<<dim3(3 * CC / 128, BB * TT / 128), 256>>>(x, W_attn);
    flash_kernel<<<dim3(TT / 64, HB_), 256>>>();
    proj_gemm_kernel<<<dim3(CC / 128, BB * TT / 128), 256>>>(W_proj, out);
}

// round 3
// speedup vs baseline: 1.2992x; 1.2992x over previous
#include <cuda_runtime.h>
#include <mma.h>
using namespace nvcuda;

#define BB  4
#define TT  2048
#define CC  1024
#define NH_ 16
#define HS_ 64
#define HB_ (BB * NH_)   // 64 (b,h) pairs

// Scratch (device globals — no allocation allowed)
__device__ float g_q[(size_t)BB * NH_ * TT * HS_];   // [B,NH,T,HS]
__device__ float g_k[(size_t)BB * NH_ * TT * HS_];
__device__ float g_v[(size_t)BB * NH_ * TT * HS_];
__device__ float g_y[(size_t)BB * TT * CC];          // [B,T,NH,HS] == [B,T,C]

// ---------------------------------------------------------------------------
// TF32 GEMM: C = A @ W^T.  A [M,CC] row-major, W [N,CC] row-major.
// Block tile 128x128, BK=32, 512 threads = 16 warps in 4x4, warp tile 32x32.
// EPI==0: qkv scatter into g_q/g_k/g_v ([B,NH,T,HS]); EPI==1: plain store,
// reading A from g_y.
// ---------------------------------------------------------------------------
template<int EPI>
__global__ __launch_bounds__(512) void gemm_tf32_kernel(
    const float* __restrict__ A, const float* __restrict__ W,
    float* __restrict__ out)
{
    __shared__ float As[128][36];   // [m][k]
    __shared__ float Bs[128][36];   // [n][k]  (W rows copied directly)

    const int tid = threadIdx.x;
    const int bn = blockIdx.x, bm = blockIdx.y;
    const int warp = tid >> 5;
    const int wm = warp >> 2, wn = warp & 3;       // 4x4 warp grid
    const int lrow = tid >> 2;                     // 0..127
    const int lcol = (tid & 3) * 8;                // 0,8,16,24

    wmma::fragment<wmma::accumulator, 16, 16, 8, float> cf[2][2];
#pragma unroll
    for (int i = 0; i < 2; i++)
#pragma unroll
        for (int j = 0; j < 2; j++) wmma::fill_fragment(cf[i][j], 0.0f);

    const float* Asrc = (EPI == 1) ? (const float*)g_y : A;
    const float* Ab = Asrc + (size_t)(bm * 128 + lrow) * CC + lcol;
    const float* Wb = W + (size_t)(bn * 128 + lrow) * CC + lcol;

    for (int k0 = 0; k0 < CC; k0 += 32) {
        float4 a0 = *(const float4*)(Ab + k0);
        float4 a1 = *(const float4*)(Ab + k0 + 4);
        float4 b0 = *(const float4*)(Wb + k0);
        float4 b1 = *(const float4*)(Wb + k0 + 4);
        __syncthreads();
        *(float4*)&As[lrow][lcol]     = a0;
        *(float4*)&As[lrow][lcol + 4] = a1;
        *(float4*)&Bs[lrow][lcol]     = b0;
        *(float4*)&Bs[lrow][lcol + 4] = b1;
        __syncthreads();
#pragma unroll
        for (int ks = 0; ks < 4; ks++) {
            wmma::fragment<wmma::matrix_a, 16, 16, 8, wmma::precision::tf32, wmma::row_major> af[2];
            wmma::fragment<wmma::matrix_b, 16, 16, 8, wmma::precision::tf32, wmma::col_major> bf[2];
#pragma unroll
            for (int i = 0; i < 2; i++) {
                wmma::load_matrix_sync(af[i], &As[wm * 32 + i * 16][ks * 8], 36);
#pragma unroll
                for (int e = 0; e < af[i].num_elements; e++)
                    af[i].x[e] = wmma::__float_to_tf32(af[i].x[e]);
            }
#pragma unroll
            for (int j = 0; j < 2; j++) {
                wmma::load_matrix_sync(bf[j], &Bs[wn * 32 + j * 16][ks * 8], 36);
#pragma unroll
                for (int e = 0; e < bf[j].num_elements; e++)
                    bf[j].x[e] = wmma::__float_to_tf32(bf[j].x[e]);
            }
#pragma unroll
            for (int i = 0; i < 2; i++)
#pragma unroll
                for (int j = 0; j < 2; j++)
                    wmma::mma_sync(cf[i][j], af[i], bf[j], cf[i][j]);
        }
    }

#pragma unroll
    for (int i = 0; i < 2; i++) {
        int m0 = bm * 128 + wm * 32 + i * 16;
#pragma unroll
        for (int j = 0; j < 2; j++) {
            int n = bn * 128 + wn * 32 + j * 16;
            if (EPI == 0) {
                int b_ = m0 >> 11;       // row / 2048
                int t  = m0 & 2047;
                int which = n >> 10;
                int c = n & 1023;
                int head = c >> 6;
                int d = c & 63;
                float* dst = (which == 0) ? g_q : ((which == 1) ? g_k : g_v);
                wmma::store_matrix_sync(
                    &dst[(((size_t)(b_ * NH_ + head)) * TT + t) * HS_ + d],
                    cf[i][j], HS_, wmma::mem_row_major);
            } else {
                wmma::store_matrix_sync(&out[(size_t)m0 * CC + n],
                                        cf[i][j], CC, wmma::mem_row_major);
            }
        }
    }
}

// ---------------------------------------------------------------------------
// Flash attention, TF32 tensor-core. One block per (head-batch, 64-query tile).
// 128 threads = 4 warps; warp w owns rows [w*16, w*16+16).
// Q preloaded into 8 A-fragments per warp (registers). Dynamic smem:
//   Ks [64][68] | Vs [64][68] | Ss [64][68]   (Q staged through Ks once)
// ---------------------------------------------------------------------------
#define FL_LD 68
#define FL_ARR (64 * FL_LD)
#define FLASH_SMEM (3 * FL_ARR * 4)

__global__ __launch_bounds__(128) void flash_tf32_kernel()
{
    extern __shared__ float sh[];
    float* Ks = sh;
    float* Vs = sh + FL_ARR;
    float* Ss = sh + 2 * FL_ARR;

    const int qt = blockIdx.x, hb = blockIdx.y;
    const int tid = threadIdx.x;
    const int warp = tid >> 5;
    const int r = tid >> 1;        // softmax row ownership (0..63)
    const int h = tid & 1;         // column half (32 cols each)

    // ---- stage Q (scaled) through Ks, pull into fragments ----
    const float* qp = g_q + ((size_t)hb * TT + qt * 64) * HS_;
#pragma unroll
    for (int u = 0; u < 8; u++) {
        float4 v = *(const float4*)(qp + r * 64 + h * 32 + u * 4);
        v.x *= 0.125f; v.y *= 0.125f; v.z *= 0.125f; v.w *= 0.125f;
        *(float4*)&Ks[r * FL_LD + h * 32 + u * 4] = v;
    }
    __syncthreads();
    wmma::fragment<wmma::matrix_a, 16, 16, 8, wmma::precision::tf32, wmma::row_major> qf[8];
#pragma unroll
    for (int ks = 0; ks < 8; ks++) {
        wmma::load_matrix_sync(qf[ks], &Ks[(warp * 16) * FL_LD + ks * 8], FL_LD);
#pragma unroll
        for (int e = 0; e < qf[ks].num_elements; e++)
            qf[ks].x[e] = wmma::__float_to_tf32(qf[ks].x[e]);
    }
    __syncthreads();   // all warps done reading Q staging before chunk 0 loads K

    float m_r = -1e30f, l_r = 0.0f;
    float O[32];
#pragma unroll
    for (int j = 0; j < 32; j++) O[j] = 0.0f;

    for (int c = 0; c <= qt; c++) {
        const float* kp = g_k + ((size_t)hb * TT + c * 64) * HS_;
        const float* vp = g_v + ((size_t)hb * TT + c * 64) * HS_;
#pragma unroll
        for (int u = 0; u < 8; u++) {
            *(float4*)&Ks[r * FL_LD + h * 32 + u * 4] =
                *(const float4*)(kp + r * 64 + h * 32 + u * 4);
            *(float4*)&Vs[r * FL_LD + h * 32 + u * 4] =
                *(const float4*)(vp + r * 64 + h * 32 + u * 4);
        }
        __syncthreads();

        // ---- S = Q K^T ----
        wmma::fragment<wmma::accumulator, 16, 16, 8, float> sc[4];
#pragma unroll
        for (int j = 0; j < 4; j++) wmma::fill_fragment(sc[j], 0.0f);
#pragma unroll
        for (int ks = 0; ks < 8; ks++) {
#pragma unroll
            for (int j = 0; j < 4; j++) {
                wmma::fragment<wmma::matrix_b, 16, 16, 8, wmma::precision::tf32, wmma::col_major> kf;
                wmma::load_matrix_sync(kf, &Ks[(j * 16) * FL_LD + ks * 8], FL_LD);
#pragma unroll
                for (int e = 0; e < kf.num_elements; e++)
                    kf.x[e] = wmma::__float_to_tf32(kf.x[e]);
                wmma::mma_sync(sc[j], qf[ks], kf, sc[j]);
            }
        }
#pragma unroll
        for (int j = 0; j < 4; j++)
            wmma::store_matrix_sync(&Ss[(warp * 16) * FL_LD + j * 16], sc[j],
                                    FL_LD, wmma::mem_row_major);
        __syncthreads();

        // ---- online softmax (2 threads per row) ----
        float p[32];
#pragma unroll
        for (int u = 0; u < 8; u++) {
            float4 s4 = *(const float4*)&Ss[r * FL_LD + h * 32 + u * 4];
            p[u * 4 + 0] = s4.x; p[u * 4 + 1] = s4.y;
            p[u * 4 + 2] = s4.z; p[u * 4 + 3] = s4.w;
        }
        if (c == qt) {
#pragma unroll
            for (int j = 0; j < 32; j++)
                if (h * 32 + j > r) p[j] = -1e30f;
        }
        float rm = -1e30f;
#pragma unroll
        for (int j = 0; j < 32; j++) rm = fmaxf(rm, p[j]);
        rm = fmaxf(rm, __shfl_xor_sync(0xffffffffu, rm, 1));
        float mnew = fmaxf(m_r, rm);
        float corr = __expf(m_r - mnew);
        float rs = 0.0f;
#pragma unroll
        for (int j = 0; j < 32; j++) { p[j] = __expf(p[j] - mnew); rs += p[j]; }
        rs += __shfl_xor_sync(0xffffffffu, rs, 1);
        l_r = l_r * corr + rs;
        m_r = mnew;
#pragma unroll
        for (int j = 0; j < 32; j++) O[j] *= corr;
#pragma unroll
        for (int u = 0; u < 8; u++) {
            float4 p4 = make_float4(p[u*4+0], p[u*4+1], p[u*4+2], p[u*4+3]);
            *(float4*)&Ss[r * FL_LD + h * 32 + u * 4] = p4;
        }
        __syncthreads();

        // ---- O += P @ V ----
        wmma::fragment<wmma::accumulator, 16, 16, 8, float> pv[4];
#pragma unroll
        for (int j = 0; j < 4; j++) wmma::fill_fragment(pv[j], 0.0f);
#pragma unroll
        for (int ks = 0; ks < 8; ks++) {
            wmma::fragment<wmma::matrix_a, 16, 16, 8, wmma::precision::tf32, wmma::row_major> pf;
            wmma::load_matrix_sync(pf, &Ss[(warp * 16) * FL_LD + ks * 8], FL_LD);
#pragma unroll
            for (int e = 0; e < pf.num_elements; e++)
                pf.x[e] = wmma::__float_to_tf32(pf.x[e]);
#pragma unroll
            for (int j = 0; j < 4; j++) {
                wmma::fragment<wmma::matrix_b, 16, 16, 8, wmma::precision::tf32, wmma::row_major> vf;
                wmma::load_matrix_sync(vf, &Vs[(ks * 8) * FL_LD + j * 16], FL_LD);
#pragma unroll
                for (int e = 0; e < vf.num_elements; e++)
                    vf.x[e] = wmma::__float_to_tf32(vf.x[e]);
                wmma::mma_sync(pv[j], pf, vf, pv[j]);
            }
        }
        // Each warp writes ONLY its own 16 rows of Ss (the rows whose P it
        // consumed) — no cross-warp hazard, warp-ordered wrt its own reads.
#pragma unroll
        for (int j = 0; j < 4; j++)
            wmma::store_matrix_sync(&Ss[(warp * 16) * FL_LD + j * 16], pv[j],
                                    FL_LD, wmma::mem_row_major);
        __syncwarp();
#pragma unroll
        for (int u = 0; u < 8; u++) {
            float4 ov = *(const float4*)&Ss[r * FL_LD + h * 32 + u * 4];
            O[u*4+0] += ov.x; O[u*4+1] += ov.y;
            O[u*4+2] += ov.z; O[u*4+3] += ov.w;
        }
        __syncthreads();   // protect Ks/Vs/Ss before next chunk
    }

    // ---- write O / l in [B,T,NH,HS] layout ----
    float inv = 1.0f / l_r;
    const int b_ = hb >> 4, head = hb & 15;
    const int t = qt * 64 + r;
    float* yp = g_y + (((size_t)(b_ * TT + t)) * NH_ + head) * HS_ + h * 32;
#pragma unroll
    for (int u = 0; u < 8; u++) {
        float4 val = make_float4(O[u*4+0]*inv, O[u*4+1]*inv,
                                 O[u*4+2]*inv, O[u*4+3]*inv);
        *(float4*)(yp + u * 4) = val;
    }
}

// ---------------------------------------------------------------------------
extern "C" void kernel_launch(void* const* d_in, const int* in_sizes, int n_in,
                              void* d_out, int out_size)
{
    const float* x      = (const float*)d_in[0];  // [B,T,C]
    const float* W_attn = (const float*)d_in[1];  // [3C,C]
    const float* W_proj = (const float*)d_in[2];  // [C,C]
    // d_in[3..6] feed a discarded branch — skipped.
    float* out = (float*)d_out;                   // [B,T,C] fp32

    cudaFuncSetAttribute(flash_tf32_kernel,
                         cudaFuncAttributeMaxDynamicSharedMemorySize, FLASH_SMEM);

    gemm_tf32_kernel<0><<<dim3(3 * CC / 128, BB * TT / 128), 512>>>(x, W_attn, nullptr);
    flash_tf32_kernel<<<dim3(TT / 64, HB_), 128, FLASH_SMEM>>>();
    gemm_tf32_kernel<1><<<dim3(CC / 128, BB * TT / 128), 512>>>(x, W_proj, out);
}

// round 4
// speedup vs baseline: 1.4130x; 1.0876x over previous
#include <cuda_runtime.h>
#include <mma.h>
using namespace nvcuda;

#define BB  4
#define TT  2048
#define CC  1024
#define NH_ 16
#define HS_ 64
#define HB_ (BB * NH_)   // 64 (b,h) pairs

// Scratch (device globals — no allocation allowed)
__device__ float g_q[(size_t)BB * NH_ * TT * HS_];   // [B,NH,T,HS]
__device__ float g_k[(size_t)BB * NH_ * TT * HS_];
__device__ float g_v[(size_t)BB * NH_ * TT * HS_];
__device__ float g_y[(size_t)BB * TT * CC];          // [B,T,NH,HS] == [B,T,C]

__device__ __forceinline__ float ftf(float x) { return wmma::__float_to_tf32(x); }
__device__ __forceinline__ float4 ftf4(float4 v) {
    return make_float4(ftf(v.x), ftf(v.y), ftf(v.z), ftf(v.w));
}
__device__ __forceinline__ float ex2(float x) {
    float r; asm("ex2.approx.ftz.f32 %0, %1;" : "=f"(r) : "f"(x)); return r;
}

// ---------------------------------------------------------------------------
// TF32 GEMM: C = A @ W^T.  A [M,CC] rm, W [N,CC] rm. Values pre-converted to
// TF32 at smem-store time; inner loop is pure LDS + HMMA.
// Block 128x128, BK=32, 256 threads = 8 warps (2m x 4n), warp tile 64x32.
// EPI==0: scatter into g_q/g_k/g_v ([B,NH,T,HS]); EPI==1: plain store from g_y.
// ---------------------------------------------------------------------------
template<int EPI>
__global__ __launch_bounds__(256) void gemm_tf32_kernel(
    const float* __restrict__ A, const float* __restrict__ W,
    float* __restrict__ out)
{
    __shared__ float As[128][36];   // [m][k], tf32 values
    __shared__ float Bs[128][36];   // [n][k], tf32 values

    const int tid = threadIdx.x;
    const int bn = blockIdx.x, bm = blockIdx.y;
    const int warp = tid >> 5;
    const int wm = warp >> 2, wn = warp & 3;   // 2 x 4 warp grid
    const int lrow = tid >> 1;                 // 0..127
    const int lcol = (tid & 1) * 16;           // 0 or 16

    wmma::fragment<wmma::accumulator, 16, 16, 8, float> cf[4][2];
#pragma unroll
    for (int i = 0; i < 4; i++)
#pragma unroll
        for (int j = 0; j < 2; j++) wmma::fill_fragment(cf[i][j], 0.0f);

    const float* Asrc = (EPI == 1) ? (const float*)g_y : A;
    const float* Ab = Asrc + (size_t)(bm * 128 + lrow) * CC + lcol;
    const float* Wb = W + (size_t)(bn * 128 + lrow) * CC + lcol;

    for (int k0 = 0; k0 < CC; k0 += 32) {
        float4 a[4], b[4];
#pragma unroll
        for (int u = 0; u < 4; u++) {
            a[u] = *(const float4*)(Ab + k0 + u * 4);
            b[u] = *(const float4*)(Wb + k0 + u * 4);
        }
        __syncthreads();
#pragma unroll
        for (int u = 0; u < 4; u++) {
            *(float4*)&As[lrow][lcol + u * 4] = ftf4(a[u]);
            *(float4*)&Bs[lrow][lcol + u * 4] = ftf4(b[u]);
        }
        __syncthreads();
#pragma unroll
        for (int ks = 0; ks < 4; ks++) {
            wmma::fragment<wmma::matrix_a, 16, 16, 8, wmma::precision::tf32, wmma::row_major> af[4];
            wmma::fragment<wmma::matrix_b, 16, 16, 8, wmma::precision::tf32, wmma::col_major> bf[2];
#pragma unroll
            for (int i = 0; i < 4; i++)
                wmma::load_matrix_sync(af[i], &As[wm * 64 + i * 16][ks * 8], 36);
#pragma unroll
            for (int j = 0; j < 2; j++)
                wmma::load_matrix_sync(bf[j], &Bs[wn * 32 + j * 16][ks * 8], 36);
#pragma unroll
            for (int i = 0; i < 4; i++)
#pragma unroll
                for (int j = 0; j < 2; j++)
                    wmma::mma_sync(cf[i][j], af[i], bf[j], cf[i][j]);
        }
    }

#pragma unroll
    for (int i = 0; i < 4; i++) {
        int m0 = bm * 128 + wm * 64 + i * 16;
#pragma unroll
        for (int j = 0; j < 2; j++) {
            int n = bn * 128 + wn * 32 + j * 16;
            if (EPI == 0) {
                int b_ = m0 >> 11;
                int t  = m0 & 2047;
                int which = n >> 10;
                int c = n & 1023;
                int head = c >> 6;
                int d = c & 63;
                float* dst = (which == 0) ? g_q : ((which == 1) ? g_k : g_v);
                wmma::store_matrix_sync(
                    &dst[(((size_t)(b_ * NH_ + head)) * TT + t) * HS_ + d],
                    cf[i][j], HS_, wmma::mem_row_major);
            } else {
                wmma::store_matrix_sync(&out[(size_t)m0 * CC + n],
                                        cf[i][j], CC, wmma::mem_row_major);
            }
        }
    }
}

// ---------------------------------------------------------------------------
// Flash attention, TF32 tensor-core. One block per (head-batch, 64-query tile).
// 128 threads = 4 warps; warp w owns rows [w*16, w*16+16) — Ss is warp-private
// bands, so only the K/V fill needs block barriers.
// K/V/Q/P all pre-converted to TF32 at smem store. exp via ex2 (log2e folded
// into the Q scale). Heavy q-tiles scheduled first.
// ---------------------------------------------------------------------------
#define FL_LD 68
#define FL_ARR (64 * FL_LD)
#define FLASH_SMEM (3 * FL_ARR * 4)

__global__ __launch_bounds__(128) void flash_tf32_kernel()
{
    extern __shared__ float sh[];
    float* Ks = sh;                 // [64][68] tf32 K (key-major)
    float* Vs = sh + FL_ARR;        // [64][68] tf32 V
    float* Ss = sh + 2 * FL_ARR;    // [64][68] warp-private S/P/PV bands

    const int qt = gridDim.x - 1 - blockIdx.x;   // heavy tiles first
    const int hb = blockIdx.y;
    const int tid = threadIdx.x;
    const int warp = tid >> 5;
    const int r = tid >> 1;        // row 0..63
    const int h = tid & 1;         // column half (32 cols)

    // ---- stage Q (scaled by 1/8 * log2e, tf32) into own Ss band ----
    const float* qp = g_q + ((size_t)hb * TT + qt * 64) * HS_;
    const float qs = 0.125f * 1.44269504f;
#pragma unroll
    for (int u = 0; u < 8; u++) {
        float4 v = *(const float4*)(qp + r * 64 + h * 32 + u * 4);
        v.x *= qs; v.y *= qs; v.z *= qs; v.w *= qs;
        *(float4*)&Ss[r * FL_LD + h * 32 + u * 4] = ftf4(v);
    }
    __syncwarp();
    wmma::fragment<wmma::matrix_a, 16, 16, 8, wmma::precision::tf32, wmma::row_major> qf[8];
#pragma unroll
    for (int ks = 0; ks < 8; ks++)
        wmma::load_matrix_sync(qf[ks], &Ss[(warp * 16) * FL_LD + ks * 8], FL_LD);
    __syncwarp();

    float m_r = -1e30f, l_r = 0.0f;
    float O[32];
#pragma unroll
    for (int j = 0; j < 32; j++) O[j] = 0.0f;

    for (int c = 0; c <= qt; c++) {
        const float* kp = g_k + ((size_t)hb * TT + c * 64) * HS_;
        const float* vp = g_v + ((size_t)hb * TT + c * 64) * HS_;
#pragma unroll
        for (int u = 0; u < 8; u++) {
            float4 kv = *(const float4*)(kp + r * 64 + h * 32 + u * 4);
            float4 vv = *(const float4*)(vp + r * 64 + h * 32 + u * 4);
            *(float4*)&Ks[r * FL_LD + h * 32 + u * 4] = ftf4(kv);
            *(float4*)&Vs[r * FL_LD + h * 32 + u * 4] = ftf4(vv);
        }
        __syncthreads();

        // ---- S = Q K^T (pure LDS + HMMA) ----
        wmma::fragment<wmma::accumulator, 16, 16, 8, float> sc[4];
#pragma unroll
        for (int j = 0; j < 4; j++) wmma::fill_fragment(sc[j], 0.0f);
#pragma unroll
        for (int ks = 0; ks < 8; ks++) {
#pragma unroll
            for (int j = 0; j < 4; j++) {
                wmma::fragment<wmma::matrix_b, 16, 16, 8, wmma::precision::tf32, wmma::col_major> kf;
                wmma::load_matrix_sync(kf, &Ks[(j * 16) * FL_LD + ks * 8], FL_LD);
                wmma::mma_sync(sc[j], qf[ks], kf, sc[j]);
            }
        }
#pragma unroll
        for (int j = 0; j < 4; j++)
            wmma::store_matrix_sync(&Ss[(warp * 16) * FL_LD + j * 16], sc[j],
                                    FL_LD, wmma::mem_row_major);
        __syncwarp();

        // ---- online softmax (2 threads per row), base-2 domain ----
        float p[32];
#pragma unroll
        for (int u = 0; u < 8; u++) {
            float4 s4 = *(const float4*)&Ss[r * FL_LD + h * 32 + u * 4];
            p[u*4+0] = s4.x; p[u*4+1] = s4.y; p[u*4+2] = s4.z; p[u*4+3] = s4.w;
        }
        if (c == qt) {
#pragma unroll
            for (int j = 0; j < 32; j++)
                if (h * 32 + j > r) p[j] = -1e30f;
        }
        float rm = -1e30f;
#pragma unroll
        for (int j = 0; j < 32; j++) rm = fmaxf(rm, p[j]);
        rm = fmaxf(rm, __shfl_xor_sync(0xffffffffu, rm, 1));
        float mnew = fmaxf(m_r, rm);
        float corr = ex2(m_r - mnew);
        float rs = 0.0f;
#pragma unroll
        for (int j = 0; j < 32; j++) { p[j] = ex2(p[j] - mnew); rs += p[j]; }
        rs += __shfl_xor_sync(0xffffffffu, rs, 1);
        l_r = l_r * corr + rs;
        m_r = mnew;
#pragma unroll
        for (int j = 0; j < 32; j++) O[j] *= corr;
#pragma unroll
        for (int u = 0; u < 8; u++) {
            float4 p4 = make_float4(ftf(p[u*4+0]), ftf(p[u*4+1]),
                                    ftf(p[u*4+2]), ftf(p[u*4+3]));
            *(float4*)&Ss[r * FL_LD + h * 32 + u * 4] = p4;
        }
        __syncwarp();

        // ---- O += P @ V ----
        wmma::fragment<wmma::accumulator, 16, 16, 8, float> pv[4];
#pragma unroll
        for (int j = 0; j < 4; j++) wmma::fill_fragment(pv[j], 0.0f);
#pragma unroll
        for (int ks = 0; ks < 8; ks++) {
            wmma::fragment<wmma::matrix_a, 16, 16, 8, wmma::precision::tf32, wmma::row_major> pf;
            wmma::load_matrix_sync(pf, &Ss[(warp * 16) * FL_LD + ks * 8], FL_LD);
#pragma unroll
            for (int j = 0; j < 4; j++) {
                wmma::fragment<wmma::matrix_b, 16, 16, 8, wmma::precision::tf32, wmma::row_major> vf;
                wmma::load_matrix_sync(vf, &Vs[(ks * 8) * FL_LD + j * 16], FL_LD);
                wmma::mma_sync(pv[j], pf, vf, pv[j]);
            }
        }
#pragma unroll
        for (int j = 0; j < 4; j++)
            wmma::store_matrix_sync(&Ss[(warp * 16) * FL_LD + j * 16], pv[j],
                                    FL_LD, wmma::mem_row_major);
        __syncwarp();
#pragma unroll
        for (int u = 0; u < 8; u++) {
            float4 ov = *(const float4*)&Ss[r * FL_LD + h * 32 + u * 4];
            O[u*4+0] += ov.x; O[u*4+1] += ov.y;
            O[u*4+2] += ov.z; O[u*4+3] += ov.w;
        }
        __syncthreads();   // all warps done with Ks/Vs before next fill
    }

    // ---- write O in [B,T,NH,HS] layout ----
    float inv = 1.0f / l_r;
    const int b_ = hb >> 4, head = hb & 15;
    const int t = qt * 64 + r;
    float* yp = g_y + (((size_t)(b_ * TT + t)) * NH_ + head) * HS_ + h * 32;
#pragma unroll
    for (int u = 0; u < 8; u++) {
        float4 val = make_float4(O[u*4+0]*inv, O[u*4+1]*inv,
                                 O[u*4+2]*inv, O[u*4+3]*inv);
        *(float4*)(yp + u * 4) = val;
    }
}

// ---------------------------------------------------------------------------
extern "C" void kernel_launch(void* const* d_in, const int* in_sizes, int n_in,
                              void* d_out, int out_size)
{
    const float* x      = (const float*)d_in[0];  // [B,T,C]
    const float* W_attn = (const float*)d_in[1];  // [3C,C]
    const float* W_proj = (const float*)d_in[2];  // [C,C]
    // d_in[3..6] feed a discarded branch — skipped.
    float* out = (float*)d_out;                   // [B,T,C] fp32

    cudaFuncSetAttribute(flash_tf32_kernel,
                         cudaFuncAttributeMaxDynamicSharedMemorySize, FLASH_SMEM);

    gemm_tf32_kernel<0><<<dim3(3 * CC / 128, BB * TT / 128), 256>>>(x, W_attn, nullptr);
    flash_tf32_kernel<<<dim3(TT / 64, HB_), 128, FLASH_SMEM>>>();
    gemm_tf32_kernel<1><<<dim3(CC / 128, BB * TT / 128), 256>>>(x, W_proj, out);
}